// round 15
// baseline (speedup 1.0000x reference)
#include <cuda_runtime.h>
#include <cuda_fp16.h>
#include <math.h>
#include <stdint.h>

#define B_ 4
#define S_ 2048
#define D_ 1024
#define F_ 4096

// ---------------- scratch (device globals: allocation-free) ----------------
__device__ __half g_scoresh[(size_t)B_ * S_ * S_];     //  32 MB fp16 raw scores
__device__ __half g_probsh [(size_t)B_ * S_ * S_];     //  32 MB fp16 probs
__device__ float  g_attn  [(size_t)B_ * S_ * D_];      //  32 MB
__device__ float  g_x     [(size_t)B_ * S_ * D_];      //  32 MB exact LN1 out
__device__ __half g_xh    [(size_t)B_ * S_ * D_];      //  16 MB fp16 LN1 out
__device__ __half g_y     [(size_t)B_ * S_ * F_];      //  64 MB fp16 gelu out
__device__ float  g_f     [(size_t)B_ * S_ * D_];      //  32 MB
__device__ __half g_hh    [(size_t)B_ * S_ * D_];      //  16 MB fp16 h   [B,S,D]
__device__ __half g_hhT   [(size_t)B_ * D_ * S_];      //  16 MB fp16 h^T [B,D,S]
__device__ __half g_w1t   [(size_t)F_ * D_];           //   8 MB fp16 w1^T [F,D]
__device__ __half g_w2t   [(size_t)D_ * F_];           //   8 MB fp16 w2^T [D,F]

// ---------------- helpers ----------------
__device__ __forceinline__ float gelu_exact(float x) {
    return 0.5f * x * (1.0f + erff(x * 0.7071067811865476f));
}
__device__ __forceinline__ float warpSum(float v) {
#pragma unroll
    for (int o = 16; o; o >>= 1) v += __shfl_xor_sync(0xffffffffu, v, o);
    return v;
}
__device__ __forceinline__ float warpMax(float v) {
#pragma unroll
    for (int o = 16; o; o >>= 1) v = fmaxf(v, __shfl_xor_sync(0xffffffffu, v, o));
    return v;
}
__device__ __forceinline__ void mma16f(float* c, const uint32_t* a, uint32_t b0, uint32_t b1) {
    asm volatile(
        "mma.sync.aligned.m16n8k16.row.col.f32.f16.f16.f32 "
        "{%0,%1,%2,%3}, {%4,%5,%6,%7}, {%8,%9}, {%0,%1,%2,%3};"
        : "+f"(c[0]), "+f"(c[1]), "+f"(c[2]), "+f"(c[3])
        : "r"(a[0]), "r"(a[1]), "r"(a[2]), "r"(a[3]), "r"(b0), "r"(b1));
}
__device__ __forceinline__ void ldsm4(uint32_t& r0, uint32_t& r1, uint32_t& r2, uint32_t& r3,
                                      uint32_t addr) {
    asm volatile("ldmatrix.sync.aligned.m8n8.x4.shared.b16 {%0,%1,%2,%3}, [%4];"
                 : "=r"(r0), "=r"(r1), "=r"(r2), "=r"(r3) : "r"(addr));
}
__device__ __forceinline__ void cpasync16(uint32_t s, const void* g) {
    asm volatile("cp.async.cg.shared.global [%0], [%1], 16;" :: "r"(s), "l"(g));
}
__device__ __forceinline__ void cp_commit() { asm volatile("cp.async.commit_group;"); }
template <int N>
__device__ __forceinline__ void cp_wait() {
    asm volatile("cp.async.wait_group %0;" :: "n"(N));
}

// ---------------- f32 -> fp16 transpose convert (+ optional direct copy) -------
__global__ void cvtHT_kernel(const float* __restrict__ src, __half* __restrict__ dstT,
                             __half* __restrict__ dstN, int R, int C) {
    __shared__ float t[32][33];
    src  += (size_t)blockIdx.z * R * C;
    dstT += (size_t)blockIdx.z * R * C;
    if (dstN) dstN += (size_t)blockIdx.z * R * C;
    const int r0 = blockIdx.y * 32, c0 = blockIdx.x * 32;
    const int tx = threadIdx.x, ty = threadIdx.y;   // 32 x 8
#pragma unroll
    for (int i = 0; i < 32; i += 8) {
        const float v = src[(size_t)(r0 + ty + i) * C + c0 + tx];
        t[ty + i][tx] = v;
        if (dstN) dstN[(size_t)(r0 + ty + i) * C + c0 + tx] = __float2half(v);
    }
    __syncthreads();
#pragma unroll
    for (int i = 0; i < 32; i += 8)
        dstT[(size_t)(c0 + ty + i) * R + r0 + tx] = __float2half(t[tx][ty + i]);
}

#define STAGE_B 16384                       // 128 rows x 128 B
#define SMEM_BYTES (3 * 2 * STAGE_B)        // 98304 B

// ---------------- FP16 GEMM: 128x128 tile, 128 threads (4 warps of 64x64) -----
// C[M,N] = epi( A[M,K] @ B[N,K]^T ), fp16 K-major, K%64==0.
// 2 CTA/SM, 3-stage cp.async ring, double-buffered ldmatrix fragments.
// EPI: 0 -> fp32 C = acc*alpha ; 1 -> fp16 C = gelu(acc+bias) ; 2 -> fp32 C = acc+bias
template <int EPI>
__global__ void __launch_bounds__(128, 2)
hf_gemm(const __half* __restrict__ A, const __half* __restrict__ B,
        void* __restrict__ Cv, int M, int N, int K,
        size_t sA, size_t sB, size_t sC,
        const float* __restrict__ bias, float alpha) {
    extern __shared__ float sm[];
    const uint32_t sb = (uint32_t)__cvta_generic_to_shared(sm);

    A += (size_t)blockIdx.z * sA;
    B += (size_t)blockIdx.z * sB;

    const int tid  = threadIdx.x;
    const int lane = tid & 31, warp = tid >> 5;     // 4 warps
    const int wm = warp >> 1, wn = warp & 1;        // 2 x 2 warp grid (64x64 tiles)

    // ---- cp.async mapping: thread t -> full row t of A and of B (8 x 16B) ----
    const __half* Ag = A + (size_t)(blockIdx.y * 128 + tid) * K;
    const __half* Bg = B + (size_t)(blockIdx.x * 128 + tid) * K;
    const uint32_t aRow = sb + (uint32_t)tid * 128;
    const uint32_t bRow = sb + 3 * STAGE_B + (uint32_t)tid * 128;
    const int rsw = tid & 7;

    auto issue = [&](int ch, int s) {
        const __half* ag = Ag + ch * 64;
        const __half* bg = Bg + ch * 64;
        const uint32_t as = aRow + s * STAGE_B;
        const uint32_t bs = bRow + s * STAGE_B;
#pragma unroll
        for (int j = 0; j < 8; j++) {
            const uint32_t off = (uint32_t)((j ^ rsw) * 16);
            cpasync16(as + off, ag + j * 8);
            cpasync16(bs + off, bg + j * 8);
        }
    };

    // ---- ldmatrix lane mapping (identical math to validated 64x32 version) ----
    const int lm = lane >> 3, ri = lane & 7;
    uint32_t aOff[4]; int aSel[4];
#pragma unroll
    for (int mt = 0; mt < 4; mt++) {
        const int r = wm * 64 + mt * 16 + (lm & 1) * 8 + ri;
        aOff[mt] = (uint32_t)r * 128;
        aSel[mt] = r & 7;
    }
    const int aCh = lm >> 1;
    uint32_t bOff[4]; int bSel[4];
#pragma unroll
    for (int np = 0; np < 4; np++) {
        const int r = wn * 64 + np * 16 + (lm >> 1) * 8 + ri;
        bOff[np] = (uint32_t)r * 128;
        bSel[np] = r & 7;
    }
    const int bCh = lm & 1;

    const int nch = K >> 6;

    issue(0, 0); cp_commit();
    issue(1, 1); cp_commit();

    float acc[4][8][4];
#pragma unroll
    for (int i = 0; i < 4; i++)
#pragma unroll
        for (int j = 0; j < 8; j++)
#pragma unroll
            for (int p = 0; p < 4; p++) acc[i][j][p] = 0.f;

    uint32_t af[2][4][4], bf[2][4][4];

    for (int ch = 0; ch < nch; ch++) {
        const int s = ch % 3;
        cp_wait<1>();
        __syncthreads();

        if (ch + 2 < nch) issue(ch + 2, (ch + 2) % 3);
        cp_commit();

        const uint32_t aSt = sb + s * STAGE_B;
        const uint32_t bSt = sb + 3 * STAGE_B + s * STAGE_B;

        // prime fragment buffer 0 (k-step 0)
#pragma unroll
        for (int mt = 0; mt < 4; mt++)
            ldsm4(af[0][mt][0], af[0][mt][1], af[0][mt][2], af[0][mt][3],
                  aSt + aOff[mt] + (uint32_t)((aCh ^ aSel[mt]) << 4));
#pragma unroll
        for (int np = 0; np < 4; np++)
            ldsm4(bf[0][np][0], bf[0][np][1], bf[0][np][2], bf[0][np][3],
                  bSt + bOff[np] + (uint32_t)((bCh ^ bSel[np]) << 4));

#pragma unroll
        for (int ks = 0; ks < 4; ks++) {
            const int cur = ks & 1, nxt = cur ^ 1;
            if (ks < 3) {   // prefetch k-step ks+1 while mma on ks
#pragma unroll
                for (int mt = 0; mt < 4; mt++)
                    ldsm4(af[nxt][mt][0], af[nxt][mt][1], af[nxt][mt][2], af[nxt][mt][3],
                          aSt + aOff[mt] + (uint32_t)(((2 * (ks + 1) + aCh) ^ aSel[mt]) << 4));
#pragma unroll
                for (int np = 0; np < 4; np++)
                    ldsm4(bf[nxt][np][0], bf[nxt][np][1], bf[nxt][np][2], bf[nxt][np][3],
                          bSt + bOff[np] + (uint32_t)(((2 * (ks + 1) + bCh) ^ bSel[np]) << 4));
            }
#pragma unroll
            for (int nt = 0; nt < 8; nt++) {
                const uint32_t b0 = bf[cur][nt >> 1][(nt & 1) * 2];
                const uint32_t b1 = bf[cur][nt >> 1][(nt & 1) * 2 + 1];
#pragma unroll
                for (int mt = 0; mt < 4; mt++) mma16f(acc[mt][nt], af[cur][mt], b0, b1);
            }
        }
    }

    // ---- epilogue ----
    const int g = lane >> 2, tig = lane & 3;
#pragma unroll
    for (int mt = 0; mt < 4; mt++) {
        const int r0 = blockIdx.y * 128 + wm * 64 + mt * 16 + g;
#pragma unroll
        for (int nt = 0; nt < 8; nt++) {
            const int c0 = blockIdx.x * 128 + wn * 64 + nt * 8 + 2 * tig;
            float v0 = acc[mt][nt][0], v1 = acc[mt][nt][1];
            float v2 = acc[mt][nt][2], v3 = acc[mt][nt][3];
            if (EPI == 0) {
                float* C = (float*)Cv + (size_t)blockIdx.z * sC;
                v0 *= alpha; v1 *= alpha; v2 *= alpha; v3 *= alpha;
                *(float2*)(C + (size_t)r0 * N + c0)       = make_float2(v0, v1);
                *(float2*)(C + (size_t)(r0 + 8) * N + c0) = make_float2(v2, v3);
            } else {
                const float bb0 = bias[c0], bb1 = bias[c0 + 1];
                v0 += bb0; v1 += bb1; v2 += bb0; v3 += bb1;
                if (EPI == 1) {
                    __half* C = (__half*)Cv + (size_t)blockIdx.z * sC;
                    v0 = gelu_exact(v0); v1 = gelu_exact(v1);
                    v2 = gelu_exact(v2); v3 = gelu_exact(v3);
                    *(__half2*)(C + (size_t)r0 * N + c0)       = __floats2half2_rn(v0, v1);
                    *(__half2*)(C + (size_t)(r0 + 8) * N + c0) = __floats2half2_rn(v2, v3);
                } else {
                    float* C = (float*)Cv + (size_t)blockIdx.z * sC;
                    *(float2*)(C + (size_t)r0 * N + c0)       = make_float2(v0, v1);
                    *(float2*)(C + (size_t)(r0 + 8) * N + c0) = make_float2(v2, v3);
                }
            }
        }
    }
}

// =================== symmetric QK^T (128x128, 256 thr, 2 CTA/SM) — round-11 =====
#define ST_STRIDE 130

__global__ void __launch_bounds__(256, 2)
hf_gemm_sym(const __half* __restrict__ Hm, __half* __restrict__ Ch,
            int Sn, int K, float alpha) {
    extern __shared__ float sm[];
    const uint32_t sb = (uint32_t)__cvta_generic_to_shared(sm);

    int t = blockIdx.x, bi = 0, rem = Sn / 128;
    while (t >= rem) { t -= rem; bi++; rem--; }
    const int bj = bi + t;

    const __half* A = Hm + (size_t)blockIdx.z * Sn * K;
    __half* C = Ch + (size_t)blockIdx.z * Sn * Sn;

    const int tid  = threadIdx.x;
    const int lane = tid & 31, warp = tid >> 5;
    const int wm = warp >> 2, wn = warp & 3;

    const int arow = tid >> 1;
    const int ac4  = (tid & 1) * 4;
    const __half* Ag = A + (size_t)(bi * 128 + arow) * K + (tid & 1) * 32;
    const __half* Bg = A + (size_t)(bj * 128 + arow) * K + (tid & 1) * 32;
    const uint32_t aRow = sb + (uint32_t)arow * 128;
    const uint32_t bRow = sb + 3 * STAGE_B + (uint32_t)arow * 128;
    const int rsw = arow & 7;

    auto issue = [&](int ch, int s) {
        const __half* ag = Ag + ch * 64;
        const __half* bg = Bg + ch * 64;
        const uint32_t as = aRow + s * STAGE_B;
        const uint32_t bs = bRow + s * STAGE_B;
#pragma unroll
        for (int j = 0; j < 4; j++) {
            const uint32_t off = (uint32_t)(((ac4 + j) ^ rsw) * 16);
            cpasync16(as + off, ag + j * 8);
            cpasync16(bs + off, bg + j * 8);
        }
    };

    const int lm = lane >> 3, ri = lane & 7;
    uint32_t aOff[4]; int aSel[4];
#pragma unroll
    for (int mt = 0; mt < 4; mt++) {
        const int r = wm * 64 + mt * 16 + (lm & 1) * 8 + ri;
        aOff[mt] = (uint32_t)r * 128;
        aSel[mt] = r & 7;
    }
    const int aCh = lm >> 1;
    uint32_t bOff[2]; int bSel[2];
#pragma unroll
    for (int np = 0; np < 2; np++) {
        const int r = wn * 32 + np * 16 + (lm >> 1) * 8 + ri;
        bOff[np] = (uint32_t)r * 128;
        bSel[np] = r & 7;
    }
    const int bCh = lm & 1;

    const int nch = K >> 6;

    issue(0, 0); cp_commit();
    issue(1, 1); cp_commit();

    float acc[4][4][4];
#pragma unroll
    for (int i = 0; i < 4; i++)
#pragma unroll
        for (int j = 0; j < 4; j++)
#pragma unroll
            for (int p = 0; p < 4; p++) acc[i][j][p] = 0.f;

    for (int ch = 0; ch < nch; ch++) {
        const int s = ch % 3;
        cp_wait<1>();
        __syncthreads();

        if (ch + 2 < nch) issue(ch + 2, (ch + 2) % 3);
        cp_commit();

        const uint32_t aSt = sb + s * STAGE_B;
        const uint32_t bSt = sb + 3 * STAGE_B + s * STAGE_B;

#pragma unroll
        for (int ks = 0; ks < 4; ks++) {
            uint32_t a[4][4];
#pragma unroll
            for (int mt = 0; mt < 4; mt++)
                ldsm4(a[mt][0], a[mt][1], a[mt][2], a[mt][3],
                      aSt + aOff[mt] + (uint32_t)(((2 * ks + aCh) ^ aSel[mt]) << 4));
            uint32_t bb[2][4];
#pragma unroll
            for (int np = 0; np < 2; np++)
                ldsm4(bb[np][0], bb[np][1], bb[np][2], bb[np][3],
                      bSt + bOff[np] + (uint32_t)(((2 * ks + bCh) ^ bSel[np]) << 4));
#pragma unroll
            for (int nt = 0; nt < 4; nt++) {
                const uint32_t b0 = bb[nt >> 1][(nt & 1) * 2];
                const uint32_t b1 = bb[nt >> 1][(nt & 1) * 2 + 1];
#pragma unroll
                for (int mt = 0; mt < 4; mt++) mma16f(acc[mt][nt], a[mt], b0, b1);
            }
        }
    }

    __syncthreads();
    __half* st = (__half*)sm;
    const int g = lane >> 2, tig = lane & 3;
#pragma unroll
    for (int mt = 0; mt < 4; mt++) {
        const int lr = wm * 64 + mt * 16 + g;
        const int r0 = bi * 128 + lr;
#pragma unroll
        for (int nt = 0; nt < 4; nt++) {
            const int lc = wn * 32 + nt * 8 + 2 * tig;
            const int c0 = bj * 128 + lc;
            const __half2 h01 = __floats2half2_rn(acc[mt][nt][0] * alpha, acc[mt][nt][1] * alpha);
            const __half2 h23 = __floats2half2_rn(acc[mt][nt][2] * alpha, acc[mt][nt][3] * alpha);
            *(__half2*)(C + (size_t)r0 * Sn + c0)       = h01;
            *(__half2*)(C + (size_t)(r0 + 8) * Sn + c0) = h23;
            *(__half2*)(st + lr * ST_STRIDE + lc)       = h01;
            *(__half2*)(st + (lr + 8) * ST_STRIDE + lc) = h23;
        }
    }

    if (bi != bj) {
        __syncthreads();
#pragma unroll
        for (int ci = 0; ci < 16; ci++) {
            const int c = warp * 16 + ci;
            __half* outp = C + (size_t)(bj * 128 + c) * Sn + bi * 128;
            const __half2 p0 = __halves2half2(st[(2 * lane) * ST_STRIDE + c],
                                              st[(2 * lane + 1) * ST_STRIDE + c]);
            const __half2 p1 = __halves2half2(st[(64 + 2 * lane) * ST_STRIDE + c],
                                              st[(64 + 2 * lane + 1) * ST_STRIDE + c]);
            *(__half2*)(outp + 2 * lane)      = p0;
            *(__half2*)(outp + 64 + 2 * lane) = p1;
        }
    }
}

// ---------------- softmax: fp16 scores + fp32 mask -> fp16 probs ----------------
__global__ void softmax_kernel(const __half* __restrict__ P, __half* __restrict__ Ph,
                               const float* __restrict__ mask) {
    __shared__ float sh[8];
    const int row = blockIdx.x;
    const int b   = row >> 11;
    const __half* p = P + (size_t)row * S_;
    __half* ph = Ph + (size_t)row * S_;
    const float* m = mask + (size_t)b * S_;
    const int tid = threadIdx.x;

    const uint4 raw = ((const uint4*)p)[tid];
    const __half2* hp = (const __half2*)&raw;
    const float4 m0 = ((const float4*)m)[2 * tid];
    const float4 m1 = ((const float4*)m)[2 * tid + 1];
    float v[8];
    {
        float2 t0 = __half22float2(hp[0]), t1 = __half22float2(hp[1]);
        float2 t2 = __half22float2(hp[2]), t3 = __half22float2(hp[3]);
        v[0] = t0.x + m0.x; v[1] = t0.y + m0.y; v[2] = t1.x + m0.z; v[3] = t1.y + m0.w;
        v[4] = t2.x + m1.x; v[5] = t2.y + m1.y; v[6] = t3.x + m1.z; v[7] = t3.y + m1.w;
    }

    float mx = v[0];
#pragma unroll
    for (int i = 1; i < 8; i++) mx = fmaxf(mx, v[i]);
    mx = warpMax(mx);
    if ((tid & 31) == 0) sh[tid >> 5] = mx;
    __syncthreads();
    mx = sh[0];
#pragma unroll
    for (int j = 1; j < 8; j++) mx = fmaxf(mx, sh[j]);

    float s = 0.f;
#pragma unroll
    for (int i = 0; i < 8; i++) { v[i] = expf(v[i] - mx); s += v[i]; }
    s = warpSum(s);
    __syncthreads();
    if ((tid & 31) == 0) sh[tid >> 5] = s;
    __syncthreads();
    s = 0.f;
#pragma unroll
    for (int j = 0; j < 8; j++) s += sh[j];
    const float inv = 1.0f / s;

    uint4 o;
    __half2* op = (__half2*)&o;
    op[0] = __floats2half2_rn(v[0] * inv, v[1] * inv);
    op[1] = __floats2half2_rn(v[2] * inv, v[3] * inv);
    op[2] = __floats2half2_rn(v[4] * inv, v[5] * inv);
    op[3] = __floats2half2_rn(v[6] * inv, v[7] * inv);
    ((uint4*)ph)[tid] = o;
}

// ---------------- out = LayerNorm(X + Y); optionally also fp16 copy ----
template <bool WR>
__global__ void add_ln_kernel(const float* __restrict__ X, const float* __restrict__ Y,
                              const float* __restrict__ gamma, const float* __restrict__ beta,
                              float* __restrict__ O, __half* __restrict__ OH) {
    __shared__ float shs[8], shq[8];
    const int row = blockIdx.x;
    const int tid = threadIdx.x;
    const size_t base = (size_t)row * D_ + tid * 4;

    const float4 a = *(const float4*)(X + base);
    const float4 b = *(const float4*)(Y + base);
    const float v0 = a.x + b.x, v1 = a.y + b.y, v2 = a.z + b.z, v3 = a.w + b.w;

    float s = v0 + v1 + v2 + v3;
    float q = v0 * v0 + v1 * v1 + v2 * v2 + v3 * v3;
    s = warpSum(s); q = warpSum(q);
    if ((tid & 31) == 0) { shs[tid >> 5] = s; shq[tid >> 5] = q; }
    __syncthreads();
    s = 0.f; q = 0.f;
#pragma unroll
    for (int j = 0; j < 8; j++) { s += shs[j]; q += shq[j]; }
    const float mean = s * (1.0f / D_);
    const float var  = q * (1.0f / D_) - mean * mean;
    const float rstd = rsqrtf(var + 1e-5f);

    const float4 gm = *(const float4*)(gamma + tid * 4);
    const float4 bt = *(const float4*)(beta  + tid * 4);
    float4 o;
    o.x = (v0 - mean) * rstd * gm.x + bt.x;
    o.y = (v1 - mean) * rstd * gm.y + bt.y;
    o.z = (v2 - mean) * rstd * gm.z + bt.z;
    o.w = (v3 - mean) * rstd * gm.w + bt.w;
    *(float4*)(O + base) = o;
    if (WR) {
        __half2 h0 = __floats2half2_rn(o.x, o.y);
        __half2 h1 = __floats2half2_rn(o.z, o.w);
        uint2 u; u.x = *(uint32_t*)&h0; u.y = *(uint32_t*)&h1;
        *(uint2*)(OH + base) = u;
    }
}

// ---------------- launch ----------------
extern "C" void kernel_launch(void* const* d_in, const int* in_sizes, int n_in,
                              void* d_out, int out_size) {
    const float* h   = (const float*)d_in[0];
    const float* msk = (const float*)d_in[1];
    const float* w1  = (const float*)d_in[2];
    const float* b1  = (const float*)d_in[3];
    const float* w2  = (const float*)d_in[4];
    const float* b2  = (const float*)d_in[5];
    const float* g1  = (const float*)d_in[6];
    const float* be1 = (const float*)d_in[7];
    const float* g2  = (const float*)d_in[8];
    const float* be2 = (const float*)d_in[9];
    float* out = (float*)d_out;

    float *attn, *x, *f;
    __half *scoresh, *probsh, *xh, *y, *hh, *hhT, *w1t, *w2t;
    cudaGetSymbolAddress((void**)&scoresh, g_scoresh);
    cudaGetSymbolAddress((void**)&probsh,  g_probsh);
    cudaGetSymbolAddress((void**)&attn,    g_attn);
    cudaGetSymbolAddress((void**)&x,       g_x);
    cudaGetSymbolAddress((void**)&xh,      g_xh);
    cudaGetSymbolAddress((void**)&y,       g_y);
    cudaGetSymbolAddress((void**)&f,       g_f);
    cudaGetSymbolAddress((void**)&hh,      g_hh);
    cudaGetSymbolAddress((void**)&hhT,     g_hhT);
    cudaGetSymbolAddress((void**)&w1t,     g_w1t);
    cudaGetSymbolAddress((void**)&w2t,     g_w2t);

    cudaFuncSetAttribute(hf_gemm<0>,  cudaFuncAttributeMaxDynamicSharedMemorySize, SMEM_BYTES);
    cudaFuncSetAttribute(hf_gemm<1>,  cudaFuncAttributeMaxDynamicSharedMemorySize, SMEM_BYTES);
    cudaFuncSetAttribute(hf_gemm<2>,  cudaFuncAttributeMaxDynamicSharedMemorySize, SMEM_BYTES);
    cudaFuncSetAttribute(hf_gemm_sym, cudaFuncAttributeMaxDynamicSharedMemorySize, SMEM_BYTES);

    // 0) fp16 conversions: h -> (hh, hhT) in one pass; w1^T, w2^T
    cvtHT_kernel<<<dim3(D_ / 32, S_ / 32, B_), dim3(32, 8)>>>(h,  hhT, hh, S_, D_);
    cvtHT_kernel<<<dim3(F_ / 32, D_ / 32, 1), dim3(32, 8)>>>(w1, w1t, nullptr, D_, F_);
    cvtHT_kernel<<<dim3(D_ / 32, F_ / 32, 1), dim3(32, 8)>>>(w2, w2t, nullptr, F_, D_);

    // 1) scores(fp16) = (h @ h^T)/sqrt(D) — symmetric upper-tri blocks
    const int ntri = (S_ / 128) * (S_ / 128 + 1) / 2;   // 136
    hf_gemm_sym<<<dim3(ntri, 1, B_), 256, SMEM_BYTES>>>(hh, scoresh, S_, D_, 0.03125f);

    // 2) probs(fp16) = softmax(scores + mask)
    softmax_kernel<<<B_ * S_, 256>>>(scoresh, probsh, msk);

    // 3) attn = probs @ h
    hf_gemm<0><<<dim3(D_ / 128, S_ / 128, B_), 128, SMEM_BYTES>>>(
        probsh, hhT, attn, S_, D_, S_,
        (size_t)S_ * S_, (size_t)D_ * S_, (size_t)S_ * D_, nullptr, 1.0f);

    // 4) x = LN1(h + attn)  (+ fp16 copy)
    add_ln_kernel<true><<<B_ * S_, 256>>>(h, attn, g1, be1, x, xh);

    // 5) y(fp16) = gelu(x @ w1 + b1)
    hf_gemm<1><<<dim3(F_ / 128, (B_ * S_) / 128, 1), 128, SMEM_BYTES>>>(
        xh, w1t, y, B_ * S_, F_, D_, 0, 0, 0, b1, 1.0f);

    // 6) f = y @ w2 + b2
    hf_gemm<2><<<dim3(D_ / 128, (B_ * S_) / 128, 1), 128, SMEM_BYTES>>>(
        y, w2t, f, B_ * S_, D_, F_, 0, 0, 0, b2, 1.0f);

    // 7) out = LN2(x + f)
    add_ln_kernel<false><<<B_ * S_, 256>>>(x, f, g2, be2, out, nullptr);
}

// round 16
// speedup vs baseline: 1.3649x; 1.3649x over previous
#include <cuda_runtime.h>
#include <cuda_fp16.h>
#include <math.h>
#include <stdint.h>

#define B_ 4
#define S_ 2048
#define D_ 1024
#define F_ 4096

// ---------------- scratch (device globals: allocation-free) ----------------
__device__ __half g_scoresh[(size_t)B_ * S_ * S_];     //  32 MB fp16 raw scores
__device__ __half g_probsh [(size_t)B_ * S_ * S_];     //  32 MB fp16 probs
__device__ __half g_attn  [(size_t)B_ * S_ * D_];      //  16 MB fp16 attn out
__device__ float  g_x     [(size_t)B_ * S_ * D_];      //  32 MB exact LN1 out
__device__ __half g_xh    [(size_t)B_ * S_ * D_];      //  16 MB fp16 LN1 out
__device__ __half g_y     [(size_t)B_ * S_ * F_];      //  64 MB fp16 gelu out
__device__ __half g_f     [(size_t)B_ * S_ * D_];      //  16 MB fp16 FFN2 out
__device__ __half g_hh    [(size_t)B_ * S_ * D_];      //  16 MB fp16 h   [B,S,D]
__device__ __half g_hhT   [(size_t)B_ * D_ * S_];      //  16 MB fp16 h^T [B,D,S]
__device__ __half g_w1t   [(size_t)F_ * D_];           //   8 MB fp16 w1^T [F,D]
__device__ __half g_w2t   [(size_t)D_ * F_];           //   8 MB fp16 w2^T [D,F]

// ---------------- helpers ----------------
__device__ __forceinline__ float gelu_exact(float x) {
    return 0.5f * x * (1.0f + erff(x * 0.7071067811865476f));
}
__device__ __forceinline__ float warpSum(float v) {
#pragma unroll
    for (int o = 16; o; o >>= 1) v += __shfl_xor_sync(0xffffffffu, v, o);
    return v;
}
__device__ __forceinline__ float warpMax(float v) {
#pragma unroll
    for (int o = 16; o; o >>= 1) v = fmaxf(v, __shfl_xor_sync(0xffffffffu, v, o));
    return v;
}
__device__ __forceinline__ void mma16f(float* c, const uint32_t* a, uint32_t b0, uint32_t b1) {
    asm volatile(
        "mma.sync.aligned.m16n8k16.row.col.f32.f16.f16.f32 "
        "{%0,%1,%2,%3}, {%4,%5,%6,%7}, {%8,%9}, {%0,%1,%2,%3};"
        : "+f"(c[0]), "+f"(c[1]), "+f"(c[2]), "+f"(c[3])
        : "r"(a[0]), "r"(a[1]), "r"(a[2]), "r"(a[3]), "r"(b0), "r"(b1));
}
__device__ __forceinline__ void ldsm4(uint32_t& r0, uint32_t& r1, uint32_t& r2, uint32_t& r3,
                                      uint32_t addr) {
    asm volatile("ldmatrix.sync.aligned.m8n8.x4.shared.b16 {%0,%1,%2,%3}, [%4];"
                 : "=r"(r0), "=r"(r1), "=r"(r2), "=r"(r3) : "r"(addr));
}
__device__ __forceinline__ void cpasync16(uint32_t s, const void* g) {
    asm volatile("cp.async.cg.shared.global [%0], [%1], 16;" :: "r"(s), "l"(g));
}
__device__ __forceinline__ void cp_commit() { asm volatile("cp.async.commit_group;"); }
template <int N>
__device__ __forceinline__ void cp_wait() {
    asm volatile("cp.async.wait_group %0;" :: "n"(N));
}

// ---------------- merged f32 -> fp16 convert/transpose (h, w1, w2 in one) ------
// flat grid: [0,8192)  h  -> hhT ([S,D]->[D,S]) + hh
//            [8192,12288)  w1 -> w1t ([D,F]->[F,D])
//            [12288,16384) w2 -> w2t ([F,D]->[D,F])
__global__ void cvtAll_kernel(const float* __restrict__ h, __half* __restrict__ hhT,
                              __half* __restrict__ hh,
                              const float* __restrict__ w1, __half* __restrict__ w1t,
                              const float* __restrict__ w2, __half* __restrict__ w2t) {
    __shared__ float t[32][33];
    const int b = blockIdx.x;
    const float* src; __half* dstT; __half* dstN = nullptr;
    int R, C, r0, c0;
    if (b < 8192) {                      // h: bx over D/32=32, by over S/32=64, bz over B
        const int bx = b & 31, by = (b >> 5) & 63, bz = b >> 11;
        src  = h   + (size_t)bz * S_ * D_;
        dstT = hhT + (size_t)bz * D_ * S_;
        dstN = hh  + (size_t)bz * S_ * D_;
        R = S_; C = D_; r0 = by * 32; c0 = bx * 32;
    } else if (b < 12288) {              // w1: bx over F/32=128, by over D/32=32
        const int tt = b - 8192;
        const int bx = tt & 127, by = tt >> 7;
        src = w1; dstT = w1t; R = D_; C = F_; r0 = by * 32; c0 = bx * 32;
    } else {                             // w2: bx over D/32=32, by over F/32=128
        const int tt = b - 12288;
        const int bx = tt & 31, by = tt >> 5;
        src = w2; dstT = w2t; R = F_; C = D_; r0 = by * 32; c0 = bx * 32;
    }
    const int tx = threadIdx.x, ty = threadIdx.y;   // 32 x 8
#pragma unroll
    for (int i = 0; i < 32; i += 8) {
        const float v = src[(size_t)(r0 + ty + i) * C + c0 + tx];
        t[ty + i][tx] = v;
        if (dstN) dstN[(size_t)(r0 + ty + i) * C + c0 + tx] = __float2half(v);
    }
    __syncthreads();
#pragma unroll
    for (int i = 0; i < 32; i += 8)
        dstT[(size_t)(c0 + ty + i) * R + r0 + tx] = __float2half(t[tx][ty + i]);
}

#define STAGE_B 16384                       // 128 rows x 128 B
#define SMEM_BYTES (3 * 2 * STAGE_B)        // 98304 B

// ---------------- FP16 mma.sync GEMM (round-11 proven config) ----------------
// C[M,N](fp16) = epi( A[M,K] @ B[N,K]^T ), fp16 K-major, K%64==0.
// 128x128 block, 256 thr, 8 warps (2x4) of 64x32, 3-stage cp.async, 2 CTA/SM.
// EPI: 0 -> C = acc*alpha ; 1 -> C = gelu(acc+bias) ; 2 -> C = acc+bias
template <int EPI>
__global__ void __launch_bounds__(256, 2)
hf_gemm(const __half* __restrict__ A, const __half* __restrict__ B,
        __half* __restrict__ Ch, int M, int N, int K,
        size_t sA, size_t sB, size_t sC,
        const float* __restrict__ bias, float alpha) {
    extern __shared__ float sm[];
    const uint32_t sb = (uint32_t)__cvta_generic_to_shared(sm);

    A += (size_t)blockIdx.z * sA;
    B += (size_t)blockIdx.z * sB;
    __half* C = Ch + (size_t)blockIdx.z * sC;

    const int tid  = threadIdx.x;
    const int lane = tid & 31, warp = tid >> 5;
    const int wm = warp >> 2, wn = warp & 3;

    const int arow = tid >> 1;
    const int ac4  = (tid & 1) * 4;
    const __half* Ag = A + (size_t)(blockIdx.y * 128 + arow) * K + (tid & 1) * 32;
    const __half* Bg = B + (size_t)(blockIdx.x * 128 + arow) * K + (tid & 1) * 32;
    const uint32_t aRow = sb + (uint32_t)arow * 128;
    const uint32_t bRow = sb + 3 * STAGE_B + (uint32_t)arow * 128;
    const int rsw = arow & 7;

    auto issue = [&](int ch, int s) {
        const __half* ag = Ag + ch * 64;
        const __half* bg = Bg + ch * 64;
        const uint32_t as = aRow + s * STAGE_B;
        const uint32_t bs = bRow + s * STAGE_B;
#pragma unroll
        for (int j = 0; j < 4; j++) {
            const uint32_t off = (uint32_t)(((ac4 + j) ^ rsw) * 16);
            cpasync16(as + off, ag + j * 8);
            cpasync16(bs + off, bg + j * 8);
        }
    };

    const int lm = lane >> 3, ri = lane & 7;
    uint32_t aOff[4]; int aSel[4];
#pragma unroll
    for (int mt = 0; mt < 4; mt++) {
        const int r = wm * 64 + mt * 16 + (lm & 1) * 8 + ri;
        aOff[mt] = (uint32_t)r * 128;
        aSel[mt] = r & 7;
    }
    const int aCh = lm >> 1;
    uint32_t bOff[2]; int bSel[2];
#pragma unroll
    for (int np = 0; np < 2; np++) {
        const int r = wn * 32 + np * 16 + (lm >> 1) * 8 + ri;
        bOff[np] = (uint32_t)r * 128;
        bSel[np] = r & 7;
    }
    const int bCh = lm & 1;

    const int nch = K >> 6;

    issue(0, 0); cp_commit();
    issue(1, 1); cp_commit();

    float acc[4][4][4];
#pragma unroll
    for (int i = 0; i < 4; i++)
#pragma unroll
        for (int j = 0; j < 4; j++)
#pragma unroll
            for (int p = 0; p < 4; p++) acc[i][j][p] = 0.f;

    for (int ch = 0; ch < nch; ch++) {
        const int s = ch % 3;
        cp_wait<1>();
        __syncthreads();

        if (ch + 2 < nch) issue(ch + 2, (ch + 2) % 3);
        cp_commit();

        const uint32_t aSt = sb + s * STAGE_B;
        const uint32_t bSt = sb + 3 * STAGE_B + s * STAGE_B;

#pragma unroll
        for (int ks = 0; ks < 4; ks++) {
            uint32_t a[4][4];
#pragma unroll
            for (int mt = 0; mt < 4; mt++)
                ldsm4(a[mt][0], a[mt][1], a[mt][2], a[mt][3],
                      aSt + aOff[mt] + (uint32_t)(((2 * ks + aCh) ^ aSel[mt]) << 4));
            uint32_t bb[2][4];
#pragma unroll
            for (int np = 0; np < 2; np++)
                ldsm4(bb[np][0], bb[np][1], bb[np][2], bb[np][3],
                      bSt + bOff[np] + (uint32_t)(((2 * ks + bCh) ^ bSel[np]) << 4));
#pragma unroll
            for (int nt = 0; nt < 4; nt++) {
                const uint32_t b0 = bb[nt >> 1][(nt & 1) * 2];
                const uint32_t b1 = bb[nt >> 1][(nt & 1) * 2 + 1];
#pragma unroll
                for (int mt = 0; mt < 4; mt++) mma16f(acc[mt][nt], a[mt], b0, b1);
            }
        }
    }

    // ---- epilogue (fp16 output for all variants) ----
    const int g = lane >> 2, tig = lane & 3;
#pragma unroll
    for (int mt = 0; mt < 4; mt++) {
        const int r0 = blockIdx.y * 128 + wm * 64 + mt * 16 + g;
#pragma unroll
        for (int nt = 0; nt < 4; nt++) {
            const int c0 = blockIdx.x * 128 + wn * 32 + nt * 8 + 2 * tig;
            float v0 = acc[mt][nt][0], v1 = acc[mt][nt][1];
            float v2 = acc[mt][nt][2], v3 = acc[mt][nt][3];
            if (EPI == 0) {
                v0 *= alpha; v1 *= alpha; v2 *= alpha; v3 *= alpha;
            } else {
                const float bb0 = bias[c0], bb1 = bias[c0 + 1];
                v0 += bb0; v1 += bb1; v2 += bb0; v3 += bb1;
                if (EPI == 1) {
                    v0 = gelu_exact(v0); v1 = gelu_exact(v1);
                    v2 = gelu_exact(v2); v3 = gelu_exact(v3);
                }
            }
            *(__half2*)(C + (size_t)r0 * N + c0)       = __floats2half2_rn(v0, v1);
            *(__half2*)(C + (size_t)(r0 + 8) * N + c0) = __floats2half2_rn(v2, v3);
        }
    }
}

// =================== symmetric QK^T (128x128, 256 thr, 2 CTA/SM) ===============
#define ST_STRIDE 130

__global__ void __launch_bounds__(256, 2)
hf_gemm_sym(const __half* __restrict__ Hm, __half* __restrict__ Ch,
            int Sn, int K, float alpha) {
    extern __shared__ float sm[];
    const uint32_t sb = (uint32_t)__cvta_generic_to_shared(sm);

    int t = blockIdx.x, bi = 0, rem = Sn / 128;
    while (t >= rem) { t -= rem; bi++; rem--; }
    const int bj = bi + t;

    const __half* A = Hm + (size_t)blockIdx.z * Sn * K;
    __half* C = Ch + (size_t)blockIdx.z * Sn * Sn;

    const int tid  = threadIdx.x;
    const int lane = tid & 31, warp = tid >> 5;
    const int wm = warp >> 2, wn = warp & 3;

    const int arow = tid >> 1;
    const int ac4  = (tid & 1) * 4;
    const __half* Ag = A + (size_t)(bi * 128 + arow) * K + (tid & 1) * 32;
    const __half* Bg = A + (size_t)(bj * 128 + arow) * K + (tid & 1) * 32;
    const uint32_t aRow = sb + (uint32_t)arow * 128;
    const uint32_t bRow = sb + 3 * STAGE_B + (uint32_t)arow * 128;
    const int rsw = arow & 7;

    auto issue = [&](int ch, int s) {
        const __half* ag = Ag + ch * 64;
        const __half* bg = Bg + ch * 64;
        const uint32_t as = aRow + s * STAGE_B;
        const uint32_t bs = bRow + s * STAGE_B;
#pragma unroll
        for (int j = 0; j < 4; j++) {
            const uint32_t off = (uint32_t)(((ac4 + j) ^ rsw) * 16);
            cpasync16(as + off, ag + j * 8);
            cpasync16(bs + off, bg + j * 8);
        }
    };

    const int lm = lane >> 3, ri = lane & 7;
    uint32_t aOff[4]; int aSel[4];
#pragma unroll
    for (int mt = 0; mt < 4; mt++) {
        const int r = wm * 64 + mt * 16 + (lm & 1) * 8 + ri;
        aOff[mt] = (uint32_t)r * 128;
        aSel[mt] = r & 7;
    }
    const int aCh = lm >> 1;
    uint32_t bOff[2]; int bSel[2];
#pragma unroll
    for (int np = 0; np < 2; np++) {
        const int r = wn * 32 + np * 16 + (lm >> 1) * 8 + ri;
        bOff[np] = (uint32_t)r * 128;
        bSel[np] = r & 7;
    }
    const int bCh = lm & 1;

    const int nch = K >> 6;

    issue(0, 0); cp_commit();
    issue(1, 1); cp_commit();

    float acc[4][4][4];
#pragma unroll
    for (int i = 0; i < 4; i++)
#pragma unroll
        for (int j = 0; j < 4; j++)
#pragma unroll
            for (int p = 0; p < 4; p++) acc[i][j][p] = 0.f;

    for (int ch = 0; ch < nch; ch++) {
        const int s = ch % 3;
        cp_wait<1>();
        __syncthreads();

        if (ch + 2 < nch) issue(ch + 2, (ch + 2) % 3);
        cp_commit();

        const uint32_t aSt = sb + s * STAGE_B;
        const uint32_t bSt = sb + 3 * STAGE_B + s * STAGE_B;

#pragma unroll
        for (int ks = 0; ks < 4; ks++) {
            uint32_t a[4][4];
#pragma unroll
            for (int mt = 0; mt < 4; mt++)
                ldsm4(a[mt][0], a[mt][1], a[mt][2], a[mt][3],
                      aSt + aOff[mt] + (uint32_t)(((2 * ks + aCh) ^ aSel[mt]) << 4));
            uint32_t bb[2][4];
#pragma unroll
            for (int np = 0; np < 2; np++)
                ldsm4(bb[np][0], bb[np][1], bb[np][2], bb[np][3],
                      bSt + bOff[np] + (uint32_t)(((2 * ks + bCh) ^ bSel[np]) << 4));
#pragma unroll
            for (int nt = 0; nt < 4; nt++) {
                const uint32_t b0 = bb[nt >> 1][(nt & 1) * 2];
                const uint32_t b1 = bb[nt >> 1][(nt & 1) * 2 + 1];
#pragma unroll
                for (int mt = 0; mt < 4; mt++) mma16f(acc[mt][nt], a[mt], b0, b1);
            }
        }
    }

    __syncthreads();
    __half* st = (__half*)sm;
    const int g = lane >> 2, tig = lane & 3;
#pragma unroll
    for (int mt = 0; mt < 4; mt++) {
        const int lr = wm * 64 + mt * 16 + g;
        const int r0 = bi * 128 + lr;
#pragma unroll
        for (int nt = 0; nt < 4; nt++) {
            const int lc = wn * 32 + nt * 8 + 2 * tig;
            const int c0 = bj * 128 + lc;
            const __half2 h01 = __floats2half2_rn(acc[mt][nt][0] * alpha, acc[mt][nt][1] * alpha);
            const __half2 h23 = __floats2half2_rn(acc[mt][nt][2] * alpha, acc[mt][nt][3] * alpha);
            *(__half2*)(C + (size_t)r0 * Sn + c0)       = h01;
            *(__half2*)(C + (size_t)(r0 + 8) * Sn + c0) = h23;
            *(__half2*)(st + lr * ST_STRIDE + lc)       = h01;
            *(__half2*)(st + (lr + 8) * ST_STRIDE + lc) = h23;
        }
    }

    if (bi != bj) {
        __syncthreads();
#pragma unroll
        for (int ci = 0; ci < 16; ci++) {
            const int c = warp * 16 + ci;
            __half* outp = C + (size_t)(bj * 128 + c) * Sn + bi * 128;
            const __half2 p0 = __halves2half2(st[(2 * lane) * ST_STRIDE + c],
                                              st[(2 * lane + 1) * ST_STRIDE + c]);
            const __half2 p1 = __halves2half2(st[(64 + 2 * lane) * ST_STRIDE + c],
                                              st[(64 + 2 * lane + 1) * ST_STRIDE + c]);
            *(__half2*)(outp + 2 * lane)      = p0;
            *(__half2*)(outp + 64 + 2 * lane) = p1;
        }
    }
}

// ---------------- softmax: fp16 scores + fp32 mask -> fp16 probs ----------------
__global__ void softmax_kernel(const __half* __restrict__ P, __half* __restrict__ Ph,
                               const float* __restrict__ mask) {
    __shared__ float sh[8];
    const int row = blockIdx.x;
    const int b   = row >> 11;
    const __half* p = P + (size_t)row * S_;
    __half* ph = Ph + (size_t)row * S_;
    const float* m = mask + (size_t)b * S_;
    const int tid = threadIdx.x;

    const uint4 raw = ((const uint4*)p)[tid];
    const __half2* hp = (const __half2*)&raw;
    const float4 m0 = ((const float4*)m)[2 * tid];
    const float4 m1 = ((const float4*)m)[2 * tid + 1];
    float v[8];
    {
        float2 t0 = __half22float2(hp[0]), t1 = __half22float2(hp[1]);
        float2 t2 = __half22float2(hp[2]), t3 = __half22float2(hp[3]);
        v[0] = t0.x + m0.x; v[1] = t0.y + m0.y; v[2] = t1.x + m0.z; v[3] = t1.y + m0.w;
        v[4] = t2.x + m1.x; v[5] = t2.y + m1.y; v[6] = t3.x + m1.z; v[7] = t3.y + m1.w;
    }

    float mx = v[0];
#pragma unroll
    for (int i = 1; i < 8; i++) mx = fmaxf(mx, v[i]);
    mx = warpMax(mx);
    if ((tid & 31) == 0) sh[tid >> 5] = mx;
    __syncthreads();
    mx = sh[0];
#pragma unroll
    for (int j = 1; j < 8; j++) mx = fmaxf(mx, sh[j]);

    float s = 0.f;
#pragma unroll
    for (int i = 0; i < 8; i++) { v[i] = expf(v[i] - mx); s += v[i]; }
    s = warpSum(s);
    __syncthreads();
    if ((tid & 31) == 0) sh[tid >> 5] = s;
    __syncthreads();
    s = 0.f;
#pragma unroll
    for (int j = 0; j < 8; j++) s += sh[j];
    const float inv = 1.0f / s;

    uint4 o;
    __half2* op = (__half2*)&o;
    op[0] = __floats2half2_rn(v[0] * inv, v[1] * inv);
    op[1] = __floats2half2_rn(v[2] * inv, v[3] * inv);
    op[2] = __floats2half2_rn(v[4] * inv, v[5] * inv);
    op[3] = __floats2half2_rn(v[6] * inv, v[7] * inv);
    ((uint4*)ph)[tid] = o;
}

// ---------------- out = LayerNorm(X + Yh), Y fp16; optionally fp16 copy ----
template <bool WR>
__global__ void add_ln_kernel(const float* __restrict__ X, const __half* __restrict__ Yh,
                              const float* __restrict__ gamma, const float* __restrict__ beta,
                              float* __restrict__ O, __half* __restrict__ OH) {
    __shared__ float shs[8], shq[8];
    const int row = blockIdx.x;
    const int tid = threadIdx.x;
    const size_t base = (size_t)row * D_ + tid * 4;

    const float4 a = *(const float4*)(X + base);
    const uint2 yr = *(const uint2*)(Yh + base);
    const float2 y0 = __half22float2(*(const __half2*)&yr.x);
    const float2 y1 = __half22float2(*(const __half2*)&yr.y);
    const float v0 = a.x + y0.x, v1 = a.y + y0.y, v2 = a.z + y1.x, v3 = a.w + y1.y;

    float s = v0 + v1 + v2 + v3;
    float q = v0 * v0 + v1 * v1 + v2 * v2 + v3 * v3;
    s = warpSum(s); q = warpSum(q);
    if ((tid & 31) == 0) { shs[tid >> 5] = s; shq[tid >> 5] = q; }
    __syncthreads();
    s = 0.f; q = 0.f;
#pragma unroll
    for (int j = 0; j < 8; j++) { s += shs[j]; q += shq[j]; }
    const float mean = s * (1.0f / D_);
    const float var  = q * (1.0f / D_) - mean * mean;
    const float rstd = rsqrtf(var + 1e-5f);

    const float4 gm = *(const float4*)(gamma + tid * 4);
    const float4 bt = *(const float4*)(beta  + tid * 4);
    float4 o;
    o.x = (v0 - mean) * rstd * gm.x + bt.x;
    o.y = (v1 - mean) * rstd * gm.y + bt.y;
    o.z = (v2 - mean) * rstd * gm.z + bt.z;
    o.w = (v3 - mean) * rstd * gm.w + bt.w;
    *(float4*)(O + base) = o;
    if (WR) {
        __half2 h0 = __floats2half2_rn(o.x, o.y);
        __half2 h1 = __floats2half2_rn(o.z, o.w);
        uint2 u; u.x = *(uint32_t*)&h0; u.y = *(uint32_t*)&h1;
        *(uint2*)(OH + base) = u;
    }
}

// ---------------- launch ----------------
extern "C" void kernel_launch(void* const* d_in, const int* in_sizes, int n_in,
                              void* d_out, int out_size) {
    const float* h   = (const float*)d_in[0];
    const float* msk = (const float*)d_in[1];
    const float* w1  = (const float*)d_in[2];
    const float* b1  = (const float*)d_in[3];
    const float* w2  = (const float*)d_in[4];
    const float* b2  = (const float*)d_in[5];
    const float* g1  = (const float*)d_in[6];
    const float* be1 = (const float*)d_in[7];
    const float* g2  = (const float*)d_in[8];
    const float* be2 = (const float*)d_in[9];
    float* out = (float*)d_out;

    float *x;
    __half *scoresh, *probsh, *attn, *xh, *y, *f, *hh, *hhT, *w1t, *w2t;
    cudaGetSymbolAddress((void**)&scoresh, g_scoresh);
    cudaGetSymbolAddress((void**)&probsh,  g_probsh);
    cudaGetSymbolAddress((void**)&attn,    g_attn);
    cudaGetSymbolAddress((void**)&x,       g_x);
    cudaGetSymbolAddress((void**)&xh,      g_xh);
    cudaGetSymbolAddress((void**)&y,       g_y);
    cudaGetSymbolAddress((void**)&f,       g_f);
    cudaGetSymbolAddress((void**)&hh,      g_hh);
    cudaGetSymbolAddress((void**)&hhT,     g_hhT);
    cudaGetSymbolAddress((void**)&w1t,     g_w1t);
    cudaGetSymbolAddress((void**)&w2t,     g_w2t);

    cudaFuncSetAttribute(hf_gemm<0>,  cudaFuncAttributeMaxDynamicSharedMemorySize, SMEM_BYTES);
    cudaFuncSetAttribute(hf_gemm<1>,  cudaFuncAttributeMaxDynamicSharedMemorySize, SMEM_BYTES);
    cudaFuncSetAttribute(hf_gemm<2>,  cudaFuncAttributeMaxDynamicSharedMemorySize, SMEM_BYTES);
    cudaFuncSetAttribute(hf_gemm_sym, cudaFuncAttributeMaxDynamicSharedMemorySize, SMEM_BYTES);

    // 0) one merged conversion kernel: h -> (hh, hhT); w1 -> w1t; w2 -> w2t
    cvtAll_kernel<<<16384, dim3(32, 8)>>>(h, hhT, hh, w1, w1t, w2, w2t);

    // 1) scores(fp16) = (h @ h^T)/sqrt(D) — symmetric upper-tri blocks
    const int ntri = (S_ / 128) * (S_ / 128 + 1) / 2;   // 136
    hf_gemm_sym<<<dim3(ntri, 1, B_), 256, SMEM_BYTES>>>(hh, scoresh, S_, D_, 0.03125f);

    // 2) probs(fp16) = softmax(scores + mask)
    softmax_kernel<<<B_ * S_, 256>>>(scoresh, probsh, msk);

    // 3) attn(fp16) = probs @ h
    hf_gemm<0><<<dim3(D_ / 128, S_ / 128, B_), 256, SMEM_BYTES>>>(
        probsh, hhT, attn, S_, D_, S_,
        (size_t)S_ * S_, (size_t)D_ * S_, (size_t)S_ * D_, nullptr, 1.0f);

    // 4) x = LN1(h + attn)  (+ fp16 copy)
    add_ln_kernel<true><<<B_ * S_, 256>>>(h, attn, g1, be1, x, xh);

    // 5) y(fp16) = gelu(x @ w1 + b1)
    hf_gemm<1><<<dim3(F_ / 128, (B_ * S_) / 128, 1), 256, SMEM_BYTES>>>(
        xh, w1t, y, B_ * S_, F_, D_, 0, 0, 0, b1, 1.0f);

    // 6) f(fp16) = y @ w2 + b2
    hf_gemm<2><<<dim3(D_ / 128, (B_ * S_) / 128, 1), 256, SMEM_BYTES>>>(
        y, w2t, f, B_ * S_, D_, F_, 0, 0, 0, b2, 1.0f);

    // 7) out = LN2(x + f)
    add_ln_kernel<false><<<B_ * S_, 256>>>(x, f, g2, be2, out, nullptr);
}